// round 11
// baseline (speedup 1.0000x reference)
#include <cuda_runtime.h>
#include <math.h>

#define Ldim 4
#define Bdim 128
#define INd  512
#define CTXd 512
#define STd  512
#define Rd   256
#define Cd   256
#define Dd   1536   // IN + CTX + ST

typedef unsigned long long u64;

// packed f32x2 helpers (Blackwell sm_103a; ptxas never emits FFMA2 from C++)
__device__ __forceinline__ u64 pack_rep(float a) {
    u64 r;
    asm("mov.b64 %0, {%1, %1};" : "=l"(r) : "f"(a));
    return r;
}
__device__ __forceinline__ void fma2(u64& acc, u64 a, u64 b) {
    asm("fma.rn.f32x2 %0, %1, %2, %0;" : "+l"(acc) : "l"(a), "l"(b));
}
__device__ __forceinline__ void unpack2(float& lo, float& hi, u64 v) {
    asm("mov.b64 {%0, %1}, %2;" : "=f"(lo), "=f"(hi) : "l"(v));
}

// ---------------- scratch (device globals; no allocation) ----------------
__device__ float g_u  [Ldim*Bdim*Rd];
__device__ float g_v  [Ldim*Bdim*Cd];
__device__ float g_ge [2*Ldim];           // sigmoid(gamma), sigmoid(eta)

// ================= fused gate GEMM + h_new epilogue =================
// A = [x | c | h[l]] read SEGMENTED directly (no concat).
// phi/alpha/beta share the A tile; h_new = sig(alpha)*tanh(phi)+sig(beta)*h.
// Tiles: 64(b) x 16(o), K-tile 32, 256 threads, 2x2 f32x2 thread tile.
// Double-buffered smem, global prefetch into registers, ONE sync per K-tile.
#define GBB 64
#define GBO 16
#define GBK 32
#define GNK (Dd/GBK)   // 48

__global__ __launch_bounds__(256) void gate_fused_kernel(
        const float* __restrict__ x,      const float* __restrict__ c,
        const float* __restrict__ h,
        const float* __restrict__ phi_w,  const float* __restrict__ alpha_w,
        const float* __restrict__ beta_w, const float* __restrict__ phi_b,
        const float* __restrict__ alpha_b,const float* __restrict__ beta_b,
        float* __restrict__ hnew) {
    __shared__ __align__(16) float As[2][GBK][GBB + 4];      // 2*2176 floats
    __shared__ __align__(16) float Ws[2][3][GBK][GBO + 4];   // 2*1920 floats  (~32KB)

    const int zt = blockIdx.y;
    const int l  = zt >> 1;
    const int bt = zt & 1;
    const int o_base = blockIdx.x * GBO;
    const int b_base = bt * GBB;

    const float* Wm[3] = {phi_w, alpha_w, beta_w};

    const int tid = threadIdx.x;       // 256
    const int tx = tid & 7;            // o-group 0..7  (x2 -> 16 o)
    const int ty = tid >> 3;           // b-group 0..31 (x2 -> 64 b)

    // per-thread load decomposition (fixed across iterations)
    const int a_bb0 = tid >> 3;              // rows 0..31
    const int a_bb1 = (tid + 256) >> 3;      // rows 32..63
    const int a_kk  = (tid & 7) << 2;
    // W: 384 float4 over 256 threads -> thread t handles t, and t+256 if t<128
    const int w_m0  = tid >> 7;              // 0..1
    const int w_r0  = tid & 127;
    const int w_m1  = (tid + 256) >> 7;      // == 2 when valid
    const int w_r1  = (tid + 256) & 127;
    const bool w_has1 = (tid < 128);

    float4 aR[2];
    float4 wR[2];

    auto prefetch = [&](int k0) {
        const float* Asrc; int Astride; int koff;
        if (k0 < INd)             { Asrc = x; Astride = INd;  koff = k0; }
        else if (k0 < INd + CTXd) { Asrc = c; Astride = CTXd; koff = k0 - INd; }
        else { Asrc = h + (size_t)l*Bdim*STd; Astride = STd; koff = k0 - INd - CTXd; }
        aR[0] = *(const float4*)(Asrc + (size_t)(b_base + a_bb0)*Astride + koff + a_kk);
        aR[1] = *(const float4*)(Asrc + (size_t)(b_base + a_bb1)*Astride + koff + a_kk);
        {
            int oo = w_r0 >> 3, kk = (w_r0 & 7) << 2;
            wR[0] = *(const float4*)(Wm[w_m0] + ((size_t)l*STd + o_base + oo)*Dd + k0 + kk);
        }
        if (w_has1) {
            int oo = w_r1 >> 3, kk = (w_r1 & 7) << 2;
            wR[1] = *(const float4*)(Wm[w_m1] + ((size_t)l*STd + o_base + oo)*Dd + k0 + kk);
        }
    };
    auto sts = [&](int p) {
        As[p][a_kk+0][a_bb0] = aR[0].x; As[p][a_kk+1][a_bb0] = aR[0].y;
        As[p][a_kk+2][a_bb0] = aR[0].z; As[p][a_kk+3][a_bb0] = aR[0].w;
        As[p][a_kk+0][a_bb1] = aR[1].x; As[p][a_kk+1][a_bb1] = aR[1].y;
        As[p][a_kk+2][a_bb1] = aR[1].z; As[p][a_kk+3][a_bb1] = aR[1].w;
        {
            int oo = w_r0 >> 3, kk = (w_r0 & 7) << 2;
            Ws[p][w_m0][kk+0][oo] = wR[0].x; Ws[p][w_m0][kk+1][oo] = wR[0].y;
            Ws[p][w_m0][kk+2][oo] = wR[0].z; Ws[p][w_m0][kk+3][oo] = wR[0].w;
        }
        if (w_has1) {
            int oo = w_r1 >> 3, kk = (w_r1 & 7) << 2;
            Ws[p][w_m1][kk+0][oo] = wR[1].x; Ws[p][w_m1][kk+1][oo] = wR[1].y;
            Ws[p][w_m1][kk+2][oo] = wR[1].z; Ws[p][w_m1][kk+3][oo] = wR[1].w;
        }
    };

    u64 acc2[3][2];
    #pragma unroll
    for (int m = 0; m < 3; m++) { acc2[m][0] = 0ull; acc2[m][1] = 0ull; }

    prefetch(0);
    int p = 0;
    for (int t = 0; t < GNK; t++) {
        sts(p);
        __syncthreads();
        if (t + 1 < GNK) prefetch((t + 1) * GBK);

        #pragma unroll
        for (int kk = 0; kk < GBK; kk++) {
            float2 a = *(const float2*)(&As[p][kk][ty*2]);
            u64 ar0 = pack_rep(a.x);
            u64 ar1 = pack_rep(a.y);
            #pragma unroll
            for (int m = 0; m < 3; m++) {
                u64 w64 = *(const u64*)(&Ws[p][m][kk][tx*2]);   // LDS.64, 8B-aligned
                fma2(acc2[m][0], ar0, w64);
                fma2(acc2[m][1], ar1, w64);
            }
        }
        p ^= 1;
    }

    // epilogue: biases, activations
    const int oo = o_base + tx*2;
    float2 pb = *(const float2*)(phi_b   + (size_t)l*STd + oo);
    float2 ab = *(const float2*)(alpha_b + (size_t)l*STd + oo);
    float2 bb = *(const float2*)(beta_b  + (size_t)l*STd + oo);
    float pbv[2] = {pb.x, pb.y};
    float abv[2] = {ab.x, ab.y};
    float bbv[2] = {bb.x, bb.y};

    #pragma unroll
    for (int i = 0; i < 2; i++) {
        int b = b_base + ty*2 + i;
        float2 hv = *(const float2*)(h + ((size_t)l*Bdim + b)*STd + oo);
        float hvv[2] = {hv.x, hv.y};
        float pacc[2], aacc[2], bacc[2];
        unpack2(pacc[0], pacc[1], acc2[0][i]);
        unpack2(aacc[0], aacc[1], acc2[1][i]);
        unpack2(bacc[0], bacc[1], acc2[2][i]);
        float2 o;
        float* op = &o.x;
        #pragma unroll
        for (int j = 0; j < 2; j++) {
            float phi = pacc[j] + pbv[j];
            float al  = 1.0f / (1.0f + expf(-(aacc[j] + abv[j])));
            float be  = 1.0f / (1.0f + expf(-(bacc[j] + bbv[j])));
            op[j] = al * tanhf(phi) + be * hvv[j];
        }
        *(float2*)(hnew + ((size_t)l*Bdim + b)*STd + oo) = o;
    }
}

// ================= u/v GEMM =================
// A = [h_new | x | c] read SEGMENTED (h_new straight from d_out).
// Tiles: 32(b) x 32(o), K-tile 32, 256 threads, 2x2 f32x2 thread tile.
// Double-buffered, one sync per K-tile. Grid = 8*2*16 = 256 blocks.
#define UBB 32
#define UBO 32
#define UBK 32
#define UNK (Dd/UBK)   // 48

__global__ __launch_bounds__(256) void uv_gemm_kernel(
        const float* __restrict__ hnew, const float* __restrict__ x,
        const float* __restrict__ c,
        const float* __restrict__ W0, const float* __restrict__ W1,
        const float* __restrict__ b0, const float* __restrict__ b1) {
    __shared__ __align__(16) float As[2][UBK][UBB + 4];   // 2*1152
    __shared__ __align__(16) float Ws[2][UBK][UBO + 4];   // 2*1152  (~18KB)

    const int m  = blockIdx.y;              // 0: u, 1: v
    const int zt = blockIdx.z;              // 0..15
    const int l  = zt >> 2;
    const int bt = zt & 3;

    const float* W    = (m == 0) ? W0 : W1;
    const float* bias = (m == 0) ? b0 : b1;
    float* out        = (m == 0) ? g_u : g_v;
    const int O = Rd;                       // Rd == Cd == 256

    const int o_base = blockIdx.x * UBO;
    const int b_base = bt * UBB;

    const float* Wblk = W + ((size_t)l*O + o_base) * Dd;

    const int tid = threadIdx.x;            // 256
    const int tx = tid & 15;                // o-group 0..15 (x2 -> 32 o)
    const int ty = tid >> 4;                // b-group 0..15 (x2 -> 32 b)

    const int ld_row = tid >> 3;            // 0..31
    const int ld_kk  = (tid & 7) << 2;

    float4 aR, wR;

    auto prefetch = [&](int k0) {
        const float* Asrc; int Astride; int koff;
        if (k0 < STd)            { Asrc = hnew + (size_t)l*Bdim*STd; Astride = STd; koff = k0; }
        else if (k0 < STd + INd) { Asrc = x; Astride = INd;  koff = k0 - STd; }
        else                     { Asrc = c; Astride = CTXd; koff = k0 - STd - INd; }
        aR = *(const float4*)(Asrc + (size_t)(b_base + ld_row)*Astride + koff + ld_kk);
        wR = *(const float4*)(Wblk + (size_t)ld_row*Dd + k0 + ld_kk);
    };
    auto sts = [&](int p) {
        As[p][ld_kk+0][ld_row] = aR.x; As[p][ld_kk+1][ld_row] = aR.y;
        As[p][ld_kk+2][ld_row] = aR.z; As[p][ld_kk+3][ld_row] = aR.w;
        Ws[p][ld_kk+0][ld_row] = wR.x; Ws[p][ld_kk+1][ld_row] = wR.y;
        Ws[p][ld_kk+2][ld_row] = wR.z; Ws[p][ld_kk+3][ld_row] = wR.w;
    };

    u64 acc2[2] = {0ull, 0ull};

    prefetch(0);
    int p = 0;
    for (int t = 0; t < UNK; t++) {
        sts(p);
        __syncthreads();
        if (t + 1 < UNK) prefetch((t + 1) * UBK);

        #pragma unroll
        for (int kk = 0; kk < UBK; kk++) {
            float2 a = *(const float2*)(&As[p][kk][ty*2]);
            u64 ar0 = pack_rep(a.x);
            u64 ar1 = pack_rep(a.y);
            u64 w   = *(const u64*)(&Ws[p][kk][tx*2]);
            fma2(acc2[0], ar0, w);
            fma2(acc2[1], ar1, w);
        }
        p ^= 1;
    }

    const int oo = o_base + tx*2;
    float2 bb2 = *(const float2*)(bias + (size_t)l*O + oo);
    float bv[2] = {bb2.x, bb2.y};
    #pragma unroll
    for (int i = 0; i < 2; i++) {
        int b = b_base + ty*2 + i;
        float r0, r1;
        unpack2(r0, r1, acc2[i]);
        float2 o;
        o.x = r0 + bv[0];
        o.y = r1 + bv[1];
        *(float2*)(out + ((size_t)l*Bdim + b)*O + oo) = o;
    }
}

// ---------------- precompute sigmoid(gamma), sigmoid(eta) ----------------
__global__ void sig_kernel(const float* __restrict__ gamma, const float* __restrict__ eta) {
    int i = threadIdx.x;
    if (i < Ldim)          g_ge[i] = 1.0f / (1.0f + expf(-gamma[i]));
    else if (i < 2*Ldim)   g_ge[i] = 1.0f / (1.0f + expf(-eta[i - Ldim]));
}

// ---------------- M update: all 4 levels per thread (neighbor reuse in registers) ----
__global__ void mupdate_kernel(const float* __restrict__ M, float* __restrict__ Mout) {
    int idx = blockIdx.x * blockDim.x + threadIdx.x;   // B*R*C/4
    int c4 = idx & 63;            // C/4 = 64
    int r  = (idx >> 6) & 255;
    int b  = idx >> 14;
    size_t base = ((size_t)b*Rd + r)*Cd + (size_t)c4*4;
    const size_t LS = (size_t)Bdim*Rd*Cd;

    float4 m[Ldim];
    #pragma unroll
    for (int l = 0; l < Ldim; l++) m[l] = *(const float4*)(M + l*LS + base);

    float uu[Ldim];
    float4 vv[Ldim];
    #pragma unroll
    for (int l = 0; l < Ldim; l++) {
        uu[l] = g_u[((size_t)l*Bdim + b)*Rd + r];
        vv[l] = *(const float4*)(g_v + ((size_t)l*Bdim + b)*Cd + (size_t)c4*4);
    }

    #pragma unroll
    for (int l = 0; l < Ldim; l++) {
        int lu = (l == 0) ? 0 : l - 1;
        int ld = (l == Ldim-1) ? Ldim-1 : l + 1;
        float g = g_ge[l];
        float e = g_ge[Ldim + l];
        float omg = 1.0f - g;
        float hg  = 0.5f * g;
        float eu  = e * uu[l];
        float4 o;
        o.x = omg*m[l].x + hg*(m[lu].x + m[ld].x) + eu*vv[l].x;
        o.y = omg*m[l].y + hg*(m[lu].y + m[ld].y) + eu*vv[l].y;
        o.z = omg*m[l].z + hg*(m[lu].z + m[ld].z) + eu*vv[l].z;
        o.w = omg*m[l].w + hg*(m[lu].w + m[ld].w) + eu*vv[l].w;
        *(float4*)(Mout + l*LS + base) = o;
    }
}

// ---------------- launch ----------------
extern "C" void kernel_launch(void* const* d_in, const int* in_sizes, int n_in,
                              void* d_out, int out_size) {
    const float* x       = (const float*)d_in[0];
    const float* c       = (const float*)d_in[1];
    const float* h       = (const float*)d_in[2];
    const float* M       = (const float*)d_in[3];
    const float* phi_w   = (const float*)d_in[4];
    const float* phi_b   = (const float*)d_in[5];
    const float* alpha_w = (const float*)d_in[6];
    const float* alpha_b = (const float*)d_in[7];
    const float* beta_w  = (const float*)d_in[8];
    const float* beta_b  = (const float*)d_in[9];
    const float* u_w     = (const float*)d_in[10];
    const float* u_b     = (const float*)d_in[11];
    const float* v_w     = (const float*)d_in[12];
    const float* v_b     = (const float*)d_in[13];
    const float* gamma   = (const float*)d_in[14];
    const float* eta     = (const float*)d_in[15];

    float* out  = (float*)d_out;
    float* hnew = out;                               // (L,B,ST)
    float* Mout = out + (size_t)Ldim*Bdim*STd;       // (L,B,R,C)

    // tiny, off-critical-path
    sig_kernel<<<1, 32>>>(gamma, eta);

    // fused phi/alpha/beta GEMM + h_new epilogue (reads x/c/h directly)
    gate_fused_kernel<<<dim3(STd/GBO, Ldim*2), 256>>>(
        x, c, h, phi_w, alpha_w, beta_w, phi_b, alpha_b, beta_b, hnew);

    // u, v (reads [h_new|x|c] directly, h_new from d_out)
    uv_gemm_kernel<<<dim3(Rd/UBO, 2, 4*Ldim), 256>>>(
        hnew, x, c, u_w, v_w, u_b, v_b);

    // M_new
    mupdate_kernel<<<(Bdim*Rd*Cd/4)/256, 256>>>(M, Mout);
}